// round 14
// baseline (speedup 1.0000x reference)
#include <cuda_runtime.h>

// Depthwise separable 4x4 blur, filter [1,3,3,1] (x) [1,3,3,1] / 64.
// Input  (8, 256, 64, 512) fp32, W-pad circular(1), H-pad reflect(1).
// Output (8, 256, 63, 511) fp32.
//
// R14 = R11's depth-8 register ring + single-wave uniform work split.
// R11's grid (2048 equal CTAs, conc 5/SM*148=740) executes as 3 lockstep
// waves for 2.77 waves of work (~8% idle tail). Here: grid = 5*numSMs CTAs,
// the 2048*63 global output rows divided evenly (~170/CTA, crossing image
// boundaries). Per-segment pipeline = R11 unchanged; dynamic segment length
// handled by blocking the consume loop in 8s so ring indices stay
// compile-time static (R4/R12/R13 lesson).

#define W      512
#define H      64
#define OW     511
#define OH     63
#define DEPTH  8
#define NIMG   2048

__device__ __forceinline__ float4 f4_vblur(const float4& a, const float4& b,
                                           const float4& c, const float4& d)
{
    float4 r;
    r.x = ((a.x + d.x) + 3.0f * (b.x + c.x)) * (1.0f / 64.0f);
    r.y = ((a.y + d.y) + 3.0f * (b.y + c.y)) * (1.0f / 64.0f);
    r.z = ((a.z + d.z) + 3.0f * (b.z + c.z)) * (1.0f / 64.0f);
    r.w = ((a.w + d.w) + 3.0f * (b.w + c.w)) * (1.0f / 64.0f);
    return r;
}

__device__ __forceinline__ float4 f4_hblur(const float4& A, const float4& B)
{
    // outputs ox = 4t+1..4t+4 from src cols A=[4t..4t+3], B=[4t+4..4t+7]
    float4 r;
    r.x = (A.x + A.w) + 3.0f * (A.y + A.z);
    r.y = (A.y + B.x) + 3.0f * (A.z + A.w);
    r.z = (A.z + B.y) + 3.0f * (A.w + B.x);
    r.w = (A.w + B.z) + 3.0f * (B.x + B.y);
    return r;
}

__global__ __launch_bounds__(128, 5) void Blur_49976239456711_kernel(
    const float* __restrict__ in, float* __restrict__ out)
{
    const int t  = threadIdx.x;            // 0..127, owns src cols 4t..4t+3
    const int cA = 4 * t;
    const int cB = (4 * t + 4) & (W - 1);  // wraps 512 -> 0 for t=127

    const int  ox0   = 4 * t + 1;
    const bool fullq = (t < 127);          // t=127 covers ox 509,510,(skip),0

    // Uniform global-output-row range for this CTA.
    const int G    = NIMG * OH;            // 129024
    const int ncta = gridDim.x;
    const int q    = G / ncta;
    const int rem  = G - q * ncta;
    int g0 = blockIdx.x * q + min(blockIdx.x, rem);
    int g1 = g0 + q + (blockIdx.x < rem ? 1 : 0);

    // 8-deep prefetch ring (persists across segments; indices always static).
    float4 pa[DEPTH], pb[DEPTH];

    while (g0 < g1) {
        const int img = g0 / OH;
        const int oya = g0 - img * OH;                 // first output row
        const int len = min(OH - oya, g1 - g0);        // outputs this segment
        g0 += len;

        const float* __restrict__ src = in  + (size_t)img * (H * W);
        float*       __restrict__ dst = out + (size_t)img * (OH * OW);

        auto issue = [&](int y, int s) {
            pa[s] = __ldcs(reinterpret_cast<const float4*>(src + y * W + cA));
            pb[s] = __ldcs(reinterpret_cast<const float4*>(src + y * W + cB));
        };
        auto store4 = [&](int oy, const float4& v) {
            float* row = dst + oy * OW;
            __stcs(row + ox0,     v.x);
            __stcs(row + ox0 + 1, v.y);
            if (fullq) {
                __stcs(row + ox0 + 2, v.z);
                __stcs(row + ox0 + 3, v.w);
            } else {
                __stcs(row + 0, v.w);       // circular wrap: ox=0
            }
        };

        // Outputs oy in [oya, oya+len). Those with oy < 62 stream src row
        // oy+2; oy == 62 (present iff oya+len == 63) reuses the window.
        const bool tail62 = (oya + len == OH);
        const int  n      = tail62 ? len - 1 : len;    // streamed outputs

        // Ring prologue: rows oya+2 .. oya+1+min(8,n) into slots 0..  .
        #pragma unroll
        for (int s = 0; s < DEPTH; ++s)
            if (s < n) issue(oya + 2 + s, s);

        // Prime vertical window: padded rows oya, oya+1, oya+2 map to src
        // rows reflect(oya-1), oya, oya+1. (oya==0 -> padded 0 = src 1.)
        float4 hb0, hb1, hb2, hb3;
        {
            const int ym1 = (oya == 0) ? 1 : oya - 1;
            float4 A = __ldcs(reinterpret_cast<const float4*>(src + ym1 * W + cA));
            float4 B = __ldcs(reinterpret_cast<const float4*>(src + ym1 * W + cB));
            hb0 = f4_hblur(A, B);
            A = __ldcs(reinterpret_cast<const float4*>(src + oya * W + cA));
            B = __ldcs(reinterpret_cast<const float4*>(src + oya * W + cB));
            hb1 = f4_hblur(A, B);
            A = __ldcs(reinterpret_cast<const float4*>(src + (oya + 1) * W + cA));
            B = __ldcs(reinterpret_cast<const float4*>(src + (oya + 1) * W + cB));
            hb2 = f4_hblur(A, B);
        }

        // Main stream: kb is a multiple of 8, so slot index == j (static).
        for (int kb = 0; kb < n; kb += DEPTH) {
            #pragma unroll
            for (int j = 0; j < DEPTH; ++j) {
                const int k = kb + j;
                if (k < n) {
                    hb3 = f4_hblur(pa[j], pb[j]);            // src row oya+2+k
                    if (k + DEPTH < n) issue(oya + 2 + k + DEPTH, j);
                    store4(oya + k, f4_vblur(hb0, hb1, hb2, hb3));
                    hb0 = hb1; hb1 = hb2; hb2 = hb3;
                }
            }
        }

        // oy = 62: padded rows 62..65 -> src 61,62,63,62 ->
        // window (hb0, hb1, hb2, hb1).
        if (tail62) {
            float4 o;
            o.x = ((hb0.x + hb1.x) + 3.0f * (hb1.x + hb2.x)) * (1.0f / 64.0f);
            o.y = ((hb0.y + hb1.y) + 3.0f * (hb1.y + hb2.y)) * (1.0f / 64.0f);
            o.z = ((hb0.z + hb1.z) + 3.0f * (hb1.z + hb2.z)) * (1.0f / 64.0f);
            o.w = ((hb0.w + hb1.w) + 3.0f * (hb1.w + hb2.w)) * (1.0f / 64.0f);
            store4(OH - 1, o);
        }
    }
}

extern "C" void kernel_launch(void* const* d_in, const int* in_sizes, int n_in,
                              void* d_out, int out_size)
{
    const float* h = (const float*)d_in[0];
    float* out = (float*)d_out;

    int dev = 0, nsm = 0;
    cudaGetDevice(&dev);
    cudaDeviceGetAttribute(&nsm, cudaDevAttrMultiProcessorCount, dev);
    if (nsm <= 0) nsm = 148;
    const int ncta = 5 * nsm;               // exactly one resident wave

    Blur_49976239456711_kernel<<<ncta, 128>>>(h, out);
}

// round 15
// speedup vs baseline: 1.3381x; 1.3381x over previous
#include <cuda_runtime.h>

// Depthwise separable 4x4 blur, filter [1,3,3,1] (x) [1,3,3,1] / 64.
// Input  (8, 256, 64, 512) fp32, W-pad circular(1), H-pad reflect(1).
// Output (8, 256, 63, 511) fp32.
//
// R15 = R11 (depth-8 register ring, ldcs/stcs, 92.6us) split into two
// FULLY STATIC half-image tasks to halve the end-of-grid drain tail:
//   top    (task even): outputs  0..31, streams src rows  2..33 (32 trips)
//   bottom (task odd):  outputs 32..62, streams src rows 34..63 (30 trips)
// All trip counts and ring indices compile-time static (R4/R12/R13/R14
// lesson). Cost: rows 31..33 read by both halves (+2.3% total traffic).

#define W      512
#define H      64
#define OW     511
#define OH     63
#define DEPTH  8

__device__ __forceinline__ float4 f4_vblur(const float4& a, const float4& b,
                                           const float4& c, const float4& d)
{
    float4 r;
    r.x = ((a.x + d.x) + 3.0f * (b.x + c.x)) * (1.0f / 64.0f);
    r.y = ((a.y + d.y) + 3.0f * (b.y + c.y)) * (1.0f / 64.0f);
    r.z = ((a.z + d.z) + 3.0f * (b.z + c.z)) * (1.0f / 64.0f);
    r.w = ((a.w + d.w) + 3.0f * (b.w + c.w)) * (1.0f / 64.0f);
    return r;
}

__device__ __forceinline__ float4 f4_hblur(const float4& A, const float4& B)
{
    // outputs ox = 4t+1..4t+4 from src cols A=[4t..4t+3], B=[4t+4..4t+7]
    float4 r;
    r.x = (A.x + A.w) + 3.0f * (A.y + A.z);
    r.y = (A.y + B.x) + 3.0f * (A.z + A.w);
    r.z = (A.z + B.y) + 3.0f * (A.w + B.x);
    r.w = (A.w + B.z) + 3.0f * (B.x + B.y);
    return r;
}

__global__ __launch_bounds__(128) void Blur_49976239456711_kernel(
    const float* __restrict__ in, float* __restrict__ out)
{
    const int t      = threadIdx.x;          // 0..127, owns src cols 4t..4t+3
    const int task   = blockIdx.x;           // 0..4095
    const int img    = task >> 1;
    const int bottom = task & 1;

    const float* __restrict__ src = in  + (size_t)img * (H * W);
    float*       __restrict__ dst = out + (size_t)img * (OH * OW);

    const int cA = 4 * t;
    const int cB = (4 * t + 4) & (W - 1);    // wraps 512 -> 0 for t=127

    const int  ox0   = 4 * t + 1;
    const bool fullq = (t < 127);            // t=127 covers ox 509,510,(skip),0

    auto store4 = [&](int oy, const float4& v) {
        float* row = dst + oy * OW;
        __stcs(row + ox0,     v.x);
        __stcs(row + ox0 + 1, v.y);
        if (fullq) {
            __stcs(row + ox0 + 2, v.z);
            __stcs(row + ox0 + 3, v.w);
        } else {
            __stcs(row + 0, v.w);            // circular wrap: ox=0
        }
    };

    auto ldrow = [&](int y, float4& A, float4& B) {
        A = __ldcs(reinterpret_cast<const float4*>(src + y * W + cA));
        B = __ldcs(reinterpret_cast<const float4*>(src + y * W + cB));
    };

    // 8-deep prefetch ring.
    float4 pa[DEPTH], pb[DEPTH];
    auto issue = [&](int y, int s) { ldrow(y, pa[s], pb[s]); };

    float4 hb0, hb1, hb2, hb3;

    if (!bottom) {
        // ── TOP: outputs 0..31, stream src rows 2..33 ──
        #pragma unroll
        for (int s = 0; s < DEPTH; ++s) issue(s + 2, s);   // rows 2..9

        // Window prime (reflect: padded 0 -> src 1, padded 1 -> src 0,
        // padded 2 -> src 1).
        float4 A1, B1, A0, B0;
        ldrow(1, A1, B1);
        ldrow(0, A0, B0);
        hb0 = f4_hblur(A1, B1);
        hb1 = f4_hblur(A0, B0);
        hb2 = hb0;

        // 32 trips @ unroll 8: slot oy&7 static. Refills rows 10..33.
        #pragma unroll 8
        for (int oy = 0; oy < 32; ++oy) {
            const int s = oy & (DEPTH - 1);
            hb3 = f4_hblur(pa[s], pb[s]);              // src row oy+2
            if (oy < 24) issue(oy + 10, s);            // rows 10..33
            store4(oy, f4_vblur(hb0, hb1, hb2, hb3));
            hb0 = hb1; hb1 = hb2; hb2 = hb3;
        }
    } else {
        // ── BOTTOM: outputs 32..62, stream src rows 34..63 ──
        #pragma unroll
        for (int s = 0; s < DEPTH; ++s) issue(s + 34, s);  // rows 34..41

        // Window prime: padded rows 32,33,34 = src rows 31,32,33.
        float4 A, B;
        ldrow(31, A, B); hb0 = f4_hblur(A, B);
        ldrow(32, A, B); hb1 = f4_hblur(A, B);
        ldrow(33, A, B); hb2 = f4_hblur(A, B);

        // 24 trips @ unroll 8 (k = 0..23), slot k&7 static.
        // Output oy = 32+k consumes src row 34+k; refill row 42+k (k<22).
        #pragma unroll 8
        for (int k = 0; k < 24; ++k) {
            const int s = k & (DEPTH - 1);
            hb3 = f4_hblur(pa[s], pb[s]);              // src row 34+k
            if (k < 22) issue(k + 42, s);              // rows 42..63
            store4(32 + k, f4_vblur(hb0, hb1, hb2, hb3));
            hb0 = hb1; hb1 = hb2; hb2 = hb3;
        }
        // Peel k = 24..29 (fully unrolled, static slots, no refills).
        #pragma unroll
        for (int k = 24; k < 30; ++k) {
            const int s = k & (DEPTH - 1);
            hb3 = f4_hblur(pa[s], pb[s]);              // src rows 58..63
            store4(32 + k, f4_vblur(hb0, hb1, hb2, hb3));
            hb0 = hb1; hb1 = hb2; hb2 = hb3;
        }

        // oy = 62: padded rows 62..65 -> src 61,62,63,62 ->
        // window (hb0, hb1, hb2, hb1).
        float4 o;
        o.x = ((hb0.x + hb1.x) + 3.0f * (hb1.x + hb2.x)) * (1.0f / 64.0f);
        o.y = ((hb0.y + hb1.y) + 3.0f * (hb1.y + hb2.y)) * (1.0f / 64.0f);
        o.z = ((hb0.z + hb1.z) + 3.0f * (hb1.z + hb2.z)) * (1.0f / 64.0f);
        o.w = ((hb0.w + hb1.w) + 3.0f * (hb1.w + hb2.w)) * (1.0f / 64.0f);
        store4(OH - 1, o);
    }
}

extern "C" void kernel_launch(void* const* d_in, const int* in_sizes, int n_in,
                              void* d_out, int out_size)
{
    const float* h = (const float*)d_in[0];
    float* out = (float*)d_out;

    const int n_task = 2 * 8 * 256;          // 4096 half-image tasks
    Blur_49976239456711_kernel<<<n_task, 128>>>(h, out);
}